// round 5
// baseline (speedup 1.0000x reference)
#include <cuda_runtime.h>
#include <math.h>

#define SEQ 8192
#define DIM 1024
#define WIN 128
#define BAND (2*WIN)   // 256

// Scratch (allowed: __device__ globals, allocated at module load, not in kernel_launch)
__device__ float g_Q[SEQ * DIM];       // 32 MB
__device__ float g_K[SEQ * DIM];       // 32 MB
__device__ float g_W[SEQ * BAND];      // 8 MB  banded exp(score)-1
__device__ float g_Xsum[DIM];          // column sums of x

// ---------------------------------------------------------------------------
// Kernel 1: Q = x @ Wq^T + bq (z=0), K = x @ Wk^T + bk (z=1)
// Classic SGEMM: BM=BN=128, BK=16, 256 threads, 8x8 accum per thread.
// Both A (x) and B (W) are row-major with K contiguous ("NT" layout).
// ---------------------------------------------------------------------------
__global__ __launch_bounds__(256) void qk_gemm(
    const float* __restrict__ x,
    const float* __restrict__ Wq, const float* __restrict__ bq,
    const float* __restrict__ Wk, const float* __restrict__ bk)
{
    const float* B; const float* bias; float* C;
    if (blockIdx.z == 0) { B = Wq; bias = bq; C = g_Q; }
    else                 { B = Wk; bias = bk; C = g_K; }
    const float* A = x;
    const int m0 = blockIdx.y * 128;
    const int n0 = blockIdx.x * 128;

    __shared__ float As[16][132];   // [k][m], padded
    __shared__ float Bs[16][132];   // [k][n], padded

    const int tid = threadIdx.x;
    const int tx = tid & 15;        // output col group (n)
    const int ty = tid >> 4;        // output row group (m)

    float acc[8][8];
    #pragma unroll
    for (int i = 0; i < 8; i++)
        #pragma unroll
        for (int j = 0; j < 8; j++) acc[i][j] = 0.f;

    for (int k0 = 0; k0 < DIM; k0 += 16) {
        // 128 rows x 16 k = 512 float4 per tile; 2 per thread per array
        #pragma unroll
        for (int t = 0; t < 2; t++) {
            int v   = tid + t * 256;
            int row = v >> 2;
            int kc  = (v & 3) << 2;
            float4 a = *(const float4*)(A + (size_t)(m0 + row) * DIM + k0 + kc);
            As[kc+0][row] = a.x; As[kc+1][row] = a.y;
            As[kc+2][row] = a.z; As[kc+3][row] = a.w;
            float4 b = *(const float4*)(B + (size_t)(n0 + row) * DIM + k0 + kc);
            Bs[kc+0][row] = b.x; Bs[kc+1][row] = b.y;
            Bs[kc+2][row] = b.z; Bs[kc+3][row] = b.w;
        }
        __syncthreads();
        #pragma unroll
        for (int k = 0; k < 16; k++) {
            float ar[8], br[8];
            *(float4*)&ar[0] = *(const float4*)&As[k][ty*8];
            *(float4*)&ar[4] = *(const float4*)&As[k][ty*8 + 4];
            *(float4*)&br[0] = *(const float4*)&Bs[k][tx*8];
            *(float4*)&br[4] = *(const float4*)&Bs[k][tx*8 + 4];
            #pragma unroll
            for (int i = 0; i < 8; i++)
                #pragma unroll
                for (int j = 0; j < 8; j++)
                    acc[i][j] += ar[i] * br[j];
        }
        __syncthreads();
    }

    float bj[8];
    #pragma unroll
    for (int j = 0; j < 8; j++) bj[j] = bias[n0 + tx*8 + j];
    #pragma unroll
    for (int i = 0; i < 8; i++) {
        float* cp = C + (size_t)(m0 + ty*8 + i) * DIM + n0 + tx*8;
        float4 c0 = make_float4(acc[i][0]+bj[0], acc[i][1]+bj[1],
                                acc[i][2]+bj[2], acc[i][3]+bj[3]);
        float4 c1 = make_float4(acc[i][4]+bj[4], acc[i][5]+bj[5],
                                acc[i][6]+bj[6], acc[i][7]+bj[7]);
        *(float4*)cp       = c0;
        *(float4*)(cp + 4) = c1;
    }
}

// ---------------------------------------------------------------------------
// Kernel 2: column sums of x (Xsum[d] = sum_s x[s][d])
// ---------------------------------------------------------------------------
__global__ void xsum_zero() { g_Xsum[blockIdx.x * 256 + threadIdx.x] = 0.f; }

__global__ void xsum_acc(const float* __restrict__ x)
{
    int d  = blockIdx.x * 256 + threadIdx.x;
    int s0 = blockIdx.y * 128;
    float sum = 0.f;
    #pragma unroll 4
    for (int i = 0; i < 128; i++)
        sum += x[(size_t)(s0 + i) * DIM + d];
    atomicAdd(&g_Xsum[d], sum);
}

// ---------------------------------------------------------------------------
// Kernel 3: banded scores. For query tile [t0, t0+128), key union is
// [t0-128, t0+256) -> 3 key subtiles of 128 (blockIdx.x = 0..2).
// Same SGEMM tile as kernel 1; epilogue writes w = expm1(score) into the
// band buffer g_W[t][s - t + 128] only for in-window, in-range (t,s).
// ---------------------------------------------------------------------------
__global__ __launch_bounds__(256) void score_gemm()
{
    const int t0 = blockIdx.y * 128;
    const int kb = t0 - WIN + blockIdx.x * 128;  // key base (may be <0 or >=SEQ)

    __shared__ float As[16][132];
    __shared__ float Bs[16][132];

    const int tid = threadIdx.x;
    const int tx = tid & 15;
    const int ty = tid >> 4;

    float acc[8][8];
    #pragma unroll
    for (int i = 0; i < 8; i++)
        #pragma unroll
        for (int j = 0; j < 8; j++) acc[i][j] = 0.f;

    for (int k0 = 0; k0 < DIM; k0 += 16) {
        #pragma unroll
        for (int t = 0; t < 2; t++) {
            int v   = tid + t * 256;
            int row = v >> 2;
            int kc  = (v & 3) << 2;
            float4 a = *(const float4*)(g_Q + (size_t)(t0 + row) * DIM + k0 + kc);
            As[kc+0][row] = a.x; As[kc+1][row] = a.y;
            As[kc+2][row] = a.z; As[kc+3][row] = a.w;
            int s = kb + row;
            float4 b = make_float4(0.f, 0.f, 0.f, 0.f);
            if (s >= 0 && s < SEQ)
                b = *(const float4*)(g_K + (size_t)s * DIM + k0 + kc);
            Bs[kc+0][row] = b.x; Bs[kc+1][row] = b.y;
            Bs[kc+2][row] = b.z; Bs[kc+3][row] = b.w;
        }
        __syncthreads();
        #pragma unroll
        for (int k = 0; k < 16; k++) {
            float ar[8], br[8];
            *(float4*)&ar[0] = *(const float4*)&As[k][ty*8];
            *(float4*)&ar[4] = *(const float4*)&As[k][ty*8 + 4];
            *(float4*)&br[0] = *(const float4*)&Bs[k][tx*8];
            *(float4*)&br[4] = *(const float4*)&Bs[k][tx*8 + 4];
            #pragma unroll
            for (int i = 0; i < 8; i++)
                #pragma unroll
                for (int j = 0; j < 8; j++)
                    acc[i][j] += ar[i] * br[j];
        }
        __syncthreads();
    }

    #pragma unroll
    for (int i = 0; i < 8; i++) {
        int t = t0 + ty*8 + i;
        #pragma unroll
        for (int j = 0; j < 8; j++) {
            int s = kb + tx*8 + j;
            if (s >= 0 && s < SEQ && s >= t - WIN && s < t + WIN)
                g_W[(size_t)t * BAND + (s - t + WIN)] = expm1f(acc[i][j]);
        }
    }
}

// ---------------------------------------------------------------------------
// Kernel 4: out[t][d] = (sum_{s in win(t)} w[t][s]*x[s][d] + Xsum[d])
//                       / (sum_{s in win(t)} w[t][s] + SEQ)
// Block tile: 64 queries x 128 d. Key union for the tile: [t0-128, t0+192),
// swept in 10 chunks of 32. Each thread also accumulates its queries' full
// denominator (it sees every s-chunk), so no extra kernel is needed.
// ---------------------------------------------------------------------------
__global__ __launch_bounds__(256) void out_kernel(
    const float* __restrict__ x, float* __restrict__ out)
{
    const int t0 = blockIdx.y * 64;
    const int d0 = blockIdx.x * 128;
    const int tid = threadIdx.x;
    const int tx = tid & 31;   // d group: d = d0 + tx*4 + {0..3}
    const int ty = tid >> 5;   // query group: t = t0 + ty*8 + {0..7}

    __shared__ float Xs[32][128];   // x rows for current s-chunk
    __shared__ float Ws[64][33];    // weights [query][s-in-chunk], padded

    float acc[8][4];
    float den[8];
    #pragma unroll
    for (int i = 0; i < 8; i++) {
        den[i] = 0.f;
        #pragma unroll
        for (int j = 0; j < 4; j++) acc[i][j] = 0.f;
    }

    const int sbase = t0 - WIN;
    for (int c = 0; c < 10; c++) {
        int sb = sbase + c * 32;
        // load x chunk: 32 rows x 128 floats = 1024 float4, 4 per thread
        #pragma unroll
        for (int t4 = 0; t4 < 4; t4++) {
            int v   = tid + t4 * 256;
            int row = v >> 5;
            int c4  = v & 31;
            int s   = sb + row;
            float4 xv = make_float4(0.f, 0.f, 0.f, 0.f);
            if (s >= 0 && s < SEQ)
                xv = *(const float4*)(x + (size_t)s * DIM + d0 + c4 * 4);
            *(float4*)&Xs[row][c4 * 4] = xv;
        }
        // load weights: 64 queries x 32 keys = 2048, 8 per thread
        #pragma unroll
        for (int t8 = 0; t8 < 8; t8++) {
            int v  = tid + t8 * 256;
            int q  = v >> 5;
            int ss = v & 31;
            int t  = t0 + q;
            int s  = sb + ss;
            float w = 0.f;
            if (s >= 0 && s < SEQ && s >= t - WIN && s < t + WIN)
                w = g_W[(size_t)t * BAND + (s - t + WIN)];
            Ws[q][ss] = w;
        }
        __syncthreads();
        #pragma unroll 4
        for (int ss = 0; ss < 32; ss++) {
            float4 xv = *(const float4*)&Xs[ss][tx * 4];
            #pragma unroll
            for (int i = 0; i < 8; i++) {
                float w = Ws[ty*8 + i][ss];
                den[i]   += w;
                acc[i][0] += w * xv.x;
                acc[i][1] += w * xv.y;
                acc[i][2] += w * xv.z;
                acc[i][3] += w * xv.w;
            }
        }
        __syncthreads();
    }

    float4 xs = *(const float4*)(g_Xsum + d0 + tx * 4);
    #pragma unroll
    for (int i = 0; i < 8; i++) {
        float dinv = 1.0f / (den[i] + (float)SEQ);
        int t = t0 + ty*8 + i;
        float4 o;
        o.x = (acc[i][0] + xs.x) * dinv;
        o.y = (acc[i][1] + xs.y) * dinv;
        o.z = (acc[i][2] + xs.z) * dinv;
        o.w = (acc[i][3] + xs.w) * dinv;
        *(float4*)(out + (size_t)t * DIM + d0 + tx * 4) = o;
    }
}

// ---------------------------------------------------------------------------
extern "C" void kernel_launch(void* const* d_in, const int* in_sizes, int n_in,
                              void* d_out, int out_size)
{
    const float* x  = (const float*)d_in[0];   // [1, 8192, 1024]
    const float* Wq = (const float*)d_in[1];   // [1024, 1024]
    const float* bq = (const float*)d_in[2];   // [1024]
    const float* Wk = (const float*)d_in[3];   // [1024, 1024]
    const float* bk = (const float*)d_in[4];   // [1024]
    float* out = (float*)d_out;                // [8192, 1024]

    // Q/K projections: 34.4 GFLOP fp32
    qk_gemm<<<dim3(DIM/128, SEQ/128, 2), 256>>>(x, Wq, bq, Wk, bk);

    // column sums of x
    xsum_zero<<<DIM/256, 256>>>();
    xsum_acc<<<dim3(DIM/256, SEQ/128), 256>>>(x);

    // banded scores -> expm1 weights
    score_gemm<<<dim3(3, SEQ/128), 256>>>();

    // banded weighted sum + softmax normalization
    out_kernel<<<dim3(DIM/128, SEQ/64), 256>>>(x, out);
}

// round 8
// speedup vs baseline: 1.8807x; 1.8807x over previous
#include <cuda_runtime.h>
#include <cuda_bf16.h>
#include <stdint.h>
#include <math.h>

#define SEQ 8192
#define DIM 1024
#define WIN 128
#define BAND 256

typedef __nv_bfloat16 bf16;

// ---------------- device global scratch ----------------
__device__ bf16 g_xh[SEQ * DIM], g_xl[SEQ * DIM];     // 16MB each
__device__ bf16 g_Wqh[DIM * DIM], g_Wql[DIM * DIM];   // 2MB each
__device__ bf16 g_Wkh[DIM * DIM], g_Wkl[DIM * DIM];
__device__ bf16 g_Qh[SEQ * DIM], g_Ql[SEQ * DIM];     // 16MB each
__device__ bf16 g_Kh[SEQ * DIM], g_Kl[SEQ * DIM];
__device__ float g_W[SEQ * BAND];                     // 8MB
__device__ float g_Xsum[DIM];

// ---------------- PTX helpers (baseline ISA only, no sm_103a features) ----
__device__ __forceinline__ uint32_t smem_u32(const void* p) {
    uint32_t r;
    asm("{ .reg .u64 t; cvta.to.shared.u64 t, %1; cvt.u32.u64 %0, t; }"
        : "=r"(r) : "l"(p));
    return r;
}
__device__ __forceinline__ void ldm_x4(uint32_t* r, uint32_t addr) {
    asm volatile("ldmatrix.sync.aligned.m8n8.x4.shared.b16 {%0,%1,%2,%3}, [%4];"
                 : "=r"(r[0]), "=r"(r[1]), "=r"(r[2]), "=r"(r[3]) : "r"(addr));
}
__device__ __forceinline__ void mma16816(float* c, const uint32_t* a, const uint32_t* b) {
    asm volatile(
        "mma.sync.aligned.m16n8k16.row.col.f32.bf16.bf16.f32 "
        "{%0,%1,%2,%3}, {%4,%5,%6,%7}, {%8,%9}, {%0,%1,%2,%3};"
        : "+f"(c[0]), "+f"(c[1]), "+f"(c[2]), "+f"(c[3])
        : "r"(a[0]), "r"(a[1]), "r"(a[2]), "r"(a[3]), "r"(b[0]), "r"(b[1]));
}

#define KPAD 40   // bf16 elements per smem row (32 data + 8 pad) -> conflict-free ldmatrix

// ---------------------------------------------------------------------------
// Shared MMA mainloop: acc[128,128] += Ah*Bh^T + Ah*Bl^T + Al*Bh^T over K=1024.
// A rows arow0..+128 always valid; B rows bounds-checked when BCHECK.
// Layout: 8 warps as 2(m) x 4(n); warp tile 64x32; k-chunk 32, 32 chunks.
// ---------------------------------------------------------------------------
template <bool BCHECK>
__device__ __forceinline__ void mma_mainloop(
    const bf16* __restrict__ Ah, const bf16* __restrict__ Al, int arow0,
    const bf16* __restrict__ Bh, const bf16* __restrict__ Bl, int brow0,
    bf16* sAh, bf16* sAl, bf16* sBh, bf16* sBl,
    float acc[4][4][4])
{
    const int tid  = threadIdx.x;
    const int lane = tid & 31;
    const int wid  = tid >> 5;
    const int wm   = wid >> 2;   // 0..1
    const int wn   = wid & 3;    // 0..3

    // ldmatrix per-lane address offsets (bytes)
    const uint32_t aoff = (((lane & 15) * KPAD) + ((lane >> 4) << 3)) * 2;
    const uint32_t boff = ((((lane & 7) + ((lane >> 4) << 3)) * KPAD) +
                           (((lane >> 3) & 1) << 3)) * 2;
    const uint32_t aAh = smem_u32(sAh) + aoff + wm * 64 * KPAD * 2;
    const uint32_t aAl = smem_u32(sAl) + aoff + wm * 64 * KPAD * 2;
    const uint32_t bBh = smem_u32(sBh) + boff + wn * 32 * KPAD * 2;
    const uint32_t bBl = smem_u32(sBl) + boff + wn * 32 * KPAD * 2;

    const int lrow = tid >> 2;        // 0..63 (+64 on second pass)
    const int lcol = (tid & 3) * 8;   // bf16 column

    for (int kc = 0; kc < 32; kc++) {
        const int k0 = kc * 32;
        #pragma unroll
        for (int i = 0; i < 2; i++) {
            int row = lrow + i * 64;
            size_t ga = (size_t)(arow0 + row) * DIM + k0 + lcol;
            *(uint4*)(sAh + row * KPAD + lcol) = *(const uint4*)(Ah + ga);
            *(uint4*)(sAl + row * KPAD + lcol) = *(const uint4*)(Al + ga);
            uint4 vh = make_uint4(0, 0, 0, 0), vl = make_uint4(0, 0, 0, 0);
            int br = brow0 + row;
            if (!BCHECK || ((unsigned)br < (unsigned)SEQ)) {
                size_t gb = (size_t)br * DIM + k0 + lcol;
                vh = *(const uint4*)(Bh + gb);
                vl = *(const uint4*)(Bl + gb);
            }
            *(uint4*)(sBh + row * KPAD + lcol) = vh;
            *(uint4*)(sBl + row * KPAD + lcol) = vl;
        }
        __syncthreads();
        #pragma unroll
        for (int ks = 0; ks < 2; ks++) {
            const uint32_t ko = ks * 32;   // 16 bf16 = 32 bytes
            uint32_t bh[2][4], bl[2][4], a[4][4];
            #pragma unroll
            for (int nf2 = 0; nf2 < 2; nf2++) {
                ldm_x4(bh[nf2], bBh + nf2 * 16 * KPAD * 2 + ko);
                ldm_x4(bl[nf2], bBl + nf2 * 16 * KPAD * 2 + ko);
            }
            #pragma unroll
            for (int mf = 0; mf < 4; mf++)
                ldm_x4(a[mf], aAh + mf * 16 * KPAD * 2 + ko);
            #pragma unroll
            for (int mf = 0; mf < 4; mf++)
                #pragma unroll
                for (int nf = 0; nf < 4; nf++) {
                    mma16816(acc[mf][nf], a[mf], &bh[nf >> 1][(nf & 1) * 2]);
                    mma16816(acc[mf][nf], a[mf], &bl[nf >> 1][(nf & 1) * 2]);
                }
            #pragma unroll
            for (int mf = 0; mf < 4; mf++)
                ldm_x4(a[mf], aAl + mf * 16 * KPAD * 2 + ko);
            #pragma unroll
            for (int mf = 0; mf < 4; mf++)
                #pragma unroll
                for (int nf = 0; nf < 4; nf++)
                    mma16816(acc[mf][nf], a[mf], &bh[nf >> 1][(nf & 1) * 2]);
        }
        __syncthreads();
    }
}

// ---------------------------------------------------------------------------
// Kernel 0: split fp32 -> bf16 hi/lo for x, Wq, Wk (one fused launch)
// ---------------------------------------------------------------------------
#define N4X (SEQ * DIM / 4)
#define N4W (DIM * DIM / 4)
__global__ void split_all(const float* __restrict__ x,
                          const float* __restrict__ Wq,
                          const float* __restrict__ Wk)
{
    int i = blockIdx.x * 256 + threadIdx.x;
    const float* s;
    bf16 *dh, *dl;
    int off;
    if (i < N4X)            { s = x;  dh = g_xh;  dl = g_xl;  off = i; }
    else if (i < N4X + N4W) { s = Wq; dh = g_Wqh; dl = g_Wql; off = i - N4X; }
    else                    { s = Wk; dh = g_Wkh; dl = g_Wkl; off = i - N4X - N4W; }
    float4 v = ((const float4*)s)[off];
    bf16 h0 = __float2bfloat16(v.x), h1 = __float2bfloat16(v.y);
    bf16 h2 = __float2bfloat16(v.z), h3 = __float2bfloat16(v.w);
    __nv_bfloat162 hh0, hh1, ll0, ll1;
    hh0.x = h0; hh0.y = h1; hh1.x = h2; hh1.y = h3;
    ll0.x = __float2bfloat16(v.x - __bfloat162float(h0));
    ll0.y = __float2bfloat16(v.y - __bfloat162float(h1));
    ll1.x = __float2bfloat16(v.z - __bfloat162float(h2));
    ll1.y = __float2bfloat16(v.w - __bfloat162float(h3));
    ((__nv_bfloat162*)dh)[2 * off]     = hh0;
    ((__nv_bfloat162*)dh)[2 * off + 1] = hh1;
    ((__nv_bfloat162*)dl)[2 * off]     = ll0;
    ((__nv_bfloat162*)dl)[2 * off + 1] = ll1;
}

// ---------------------------------------------------------------------------
// Kernel 1: Q/K projection (tensor cores). z=0 -> Q, z=1 -> K.
// Epilogue adds bias, stores Q/K directly as bf16 hi/lo splits.
// ---------------------------------------------------------------------------
__global__ __launch_bounds__(256) void qk_mma(const float* __restrict__ bq,
                                              const float* __restrict__ bk)
{
    __shared__ bf16 sAh[128 * KPAD], sAl[128 * KPAD];
    __shared__ bf16 sBh[128 * KPAD], sBl[128 * KPAD];

    const int n0 = blockIdx.x * 128;
    const int m0 = blockIdx.y * 128;
    const bool isK = (blockIdx.z != 0);
    const bf16* Bh = isK ? g_Wkh : g_Wqh;
    const bf16* Bl = isK ? g_Wkl : g_Wql;
    const float* bias = isK ? bk : bq;
    bf16* Oh = isK ? g_Kh : g_Qh;
    bf16* Ol = isK ? g_Kl : g_Ql;

    float acc[4][4][4];
    #pragma unroll
    for (int a = 0; a < 4; a++)
        #pragma unroll
        for (int b = 0; b < 4; b++)
            #pragma unroll
            for (int c = 0; c < 4; c++) acc[a][b][c] = 0.f;

    mma_mainloop<false>(g_xh, g_xl, m0, Bh, Bl, n0, sAh, sAl, sBh, sBl, acc);

    const int lane = threadIdx.x & 31;
    const int wid  = threadIdx.x >> 5;
    const int wm = wid >> 2, wn = wid & 3;
    const int g = lane >> 2, t2 = (lane & 3) * 2;

    #pragma unroll
    for (int mf = 0; mf < 4; mf++) {
        int row = m0 + wm * 64 + mf * 16 + g;
        #pragma unroll
        for (int nf = 0; nf < 4; nf++) {
            int col = n0 + wn * 32 + nf * 8 + t2;
            float b0 = bias[col], b1 = bias[col + 1];
            #pragma unroll
            for (int h = 0; h < 2; h++) {   // h=0: rows g, h=1: rows g+8
                float v0 = acc[mf][nf][2 * h]     + b0;
                float v1 = acc[mf][nf][2 * h + 1] + b1;
                bf16 h0 = __float2bfloat16(v0), h1 = __float2bfloat16(v1);
                __nv_bfloat162 hh, ll;
                hh.x = h0; hh.y = h1;
                ll.x = __float2bfloat16(v0 - __bfloat162float(h0));
                ll.y = __float2bfloat16(v1 - __bfloat162float(h1));
                size_t o = (size_t)(row + 8 * h) * DIM + col;
                *(__nv_bfloat162*)(Oh + o) = hh;
                *(__nv_bfloat162*)(Ol + o) = ll;
            }
        }
    }
}

// ---------------------------------------------------------------------------
// Kernel 2: banded scores (tensor cores). 3 key subtiles per 128-query tile.
// Epilogue: expm1(score) into band buffer g_W.
// ---------------------------------------------------------------------------
__global__ __launch_bounds__(256) void score_mma()
{
    __shared__ bf16 sAh[128 * KPAD], sAl[128 * KPAD];
    __shared__ bf16 sBh[128 * KPAD], sBl[128 * KPAD];

    const int t0 = blockIdx.y * 128;
    const int kb = t0 - WIN + blockIdx.x * 128;

    float acc[4][4][4];
    #pragma unroll
    for (int a = 0; a < 4; a++)
        #pragma unroll
        for (int b = 0; b < 4; b++)
            #pragma unroll
            for (int c = 0; c < 4; c++) acc[a][b][c] = 0.f;

    mma_mainloop<true>(g_Qh, g_Ql, t0, g_Kh, g_Kl, kb, sAh, sAl, sBh, sBl, acc);

    const int lane = threadIdx.x & 31;
    const int wid  = threadIdx.x >> 5;
    const int wm = wid >> 2, wn = wid & 3;
    const int g = lane >> 2, t2 = (lane & 3) * 2;

    #pragma unroll
    for (int mf = 0; mf < 4; mf++) {
        #pragma unroll
        for (int nf = 0; nf < 4; nf++) {
            int s = kb + wn * 32 + nf * 8 + t2;
            if ((unsigned)s >= (unsigned)SEQ && (unsigned)(s + 1) >= (unsigned)SEQ)
                continue;
            #pragma unroll
            for (int h = 0; h < 2; h++) {
                int t = t0 + wm * 64 + mf * 16 + g + 8 * h;
                int j0 = s - t + WIN;
                if ((unsigned)s < (unsigned)SEQ && (unsigned)j0 < (unsigned)BAND)
                    g_W[(size_t)t * BAND + j0] = expm1f(acc[mf][nf][2 * h]);
                int j1 = j0 + 1;
                if ((unsigned)(s + 1) < (unsigned)SEQ && (unsigned)j1 < (unsigned)BAND)
                    g_W[(size_t)t * BAND + j1] = expm1f(acc[mf][nf][2 * h + 1]);
            }
        }
    }
}

// ---------------------------------------------------------------------------
// Kernel 3: column sums of x
// ---------------------------------------------------------------------------
__global__ void xsum_zero() { g_Xsum[blockIdx.x * 256 + threadIdx.x] = 0.f; }

__global__ void xsum_acc(const float* __restrict__ x)
{
    int d  = blockIdx.x * 256 + threadIdx.x;
    int s0 = blockIdx.y * 128;
    float sum = 0.f;
    #pragma unroll 4
    for (int i = 0; i < 128; i++)
        sum += x[(size_t)(s0 + i) * DIM + d];
    atomicAdd(&g_Xsum[d], sum);
}

// ---------------------------------------------------------------------------
// Kernel 4: out[t][d] = (sum_s w[t][s] x[s][d] + Xsum[d]) / (sum_s w + SEQ)
// SGEMM-style 128x128 tile, BK=16, 256 threads, 8x8 accum + per-query denom.
// ---------------------------------------------------------------------------
__global__ __launch_bounds__(256) void out_kernel(const float* __restrict__ x,
                                                  float* __restrict__ out)
{
    const int t0 = blockIdx.y * 128;
    const int d0 = blockIdx.x * 128;
    const int tid = threadIdx.x;
    const int tx = tid & 15;
    const int ty = tid >> 4;

    __shared__ float Ws[16][132];
    __shared__ float Xs[16][132];

    float acc[8][8];
    float den[8];
    #pragma unroll
    for (int i = 0; i < 8; i++) {
        den[i] = 0.f;
        #pragma unroll
        for (int j = 0; j < 8; j++) acc[i][j] = 0.f;
    }

    for (int c = 0; c < 24; c++) {
        const int sbk = t0 - WIN + c * 16;
        #pragma unroll
        for (int i = 0; i < 2; i++) {
            int v = tid + i * 256;
            int row = v >> 5, c4 = v & 31;
            int s = sbk + row;
            float4 xv = make_float4(0.f, 0.f, 0.f, 0.f);
            if ((unsigned)s < (unsigned)SEQ)
                xv = *(const float4*)(x + (size_t)s * DIM + d0 + c4 * 4);
            *(float4*)&Xs[row][c4 * 4] = xv;
        }
        #pragma unroll
        for (int i = 0; i < 8; i++) {
            int v = tid + i * 256;
            int q = v >> 4, k = v & 15;
            int t = t0 + q;
            int s = sbk + k;
            int j = s - t + WIN;
            float w = 0.f;
            if ((unsigned)s < (unsigned)SEQ && (unsigned)j < (unsigned)BAND)
                w = g_W[(size_t)t * BAND + j];
            Ws[k][q] = w;
        }
        __syncthreads();
        #pragma unroll
        for (int k = 0; k < 16; k++) {
            float ar[8], br[8];
            *(float4*)&ar[0] = *(const float4*)&Ws[k][ty * 8];
            *(float4*)&ar[4] = *(const float4*)&Ws[k][ty * 8 + 4];
            *(float4*)&br[0] = *(const float4*)&Xs[k][tx * 8];
            *(float4*)&br[4] = *(const float4*)&Xs[k][tx * 8 + 4];
            #pragma unroll
            for (int i = 0; i < 8; i++) {
                den[i] += ar[i];
                #pragma unroll
                for (int j = 0; j < 8; j++)
                    acc[i][j] += ar[i] * br[j];
            }
        }
        __syncthreads();
    }

    float xs[8];
    *(float4*)&xs[0] = *(const float4*)(g_Xsum + d0 + tx * 8);
    *(float4*)&xs[4] = *(const float4*)(g_Xsum + d0 + tx * 8 + 4);
    #pragma unroll
    for (int i = 0; i < 8; i++) {
        float dinv = 1.0f / (den[i] + (float)SEQ);
        float* op = out + (size_t)(t0 + ty * 8 + i) * DIM + d0 + tx * 8;
        float4 o0 = make_float4((acc[i][0] + xs[0]) * dinv, (acc[i][1] + xs[1]) * dinv,
                                (acc[i][2] + xs[2]) * dinv, (acc[i][3] + xs[3]) * dinv);
        float4 o1 = make_float4((acc[i][4] + xs[4]) * dinv, (acc[i][5] + xs[5]) * dinv,
                                (acc[i][6] + xs[6]) * dinv, (acc[i][7] + xs[7]) * dinv);
        *(float4*)op       = o0;
        *(float4*)(op + 4) = o1;
    }
}

// ---------------------------------------------------------------------------
extern "C" void kernel_launch(void* const* d_in, const int* in_sizes, int n_in,
                              void* d_out, int out_size)
{
    const float* x  = (const float*)d_in[0];
    const float* Wq = (const float*)d_in[1];
    const float* bq = (const float*)d_in[2];
    const float* Wk = (const float*)d_in[3];
    const float* bk = (const float*)d_in[4];
    float* out = (float*)d_out;

    // 0) fp32 -> bf16 hi/lo splits of x, Wq, Wk
    split_all<<<(N4X + 2 * N4W) / 256, 256>>>(x, Wq, Wk);

    // 1) Q/K projections on tensor cores (3-term split-bf16 emulated fp32)
    qk_mma<<<dim3(DIM / 128, SEQ / 128, 2), 256>>>(bq, bk);

    // 2) column sums of x
    xsum_zero<<<DIM / 256, 256>>>();
    xsum_acc<<<dim3(DIM / 256, SEQ / 128), 256>>>(x);

    // 3) banded scores -> expm1 weights, on tensor cores
    score_mma<<<dim3(3, SEQ / 128), 256>>>();

    // 4) banded weighted sum + normalization (fp32 FFMA)
    out_kernel<<<dim3(DIM / 128, SEQ / 128), 256>>>(x, out);
}

// round 9
// speedup vs baseline: 1.8841x; 1.0018x over previous
#include <cuda_runtime.h>
#include <cuda_bf16.h>
#include <stdint.h>
#include <math.h>

#define SEQ 8192
#define DIM 1024
#define WIN 128
#define BAND 256

typedef __nv_bfloat16 bf16;

// ---------------- device global scratch ----------------
__device__ bf16 g_xh[SEQ * DIM], g_xl[SEQ * DIM];     // 16MB each
__device__ bf16 g_Wqh[DIM * DIM], g_Wql[DIM * DIM];   // 2MB each
__device__ bf16 g_Wkh[DIM * DIM], g_Wkl[DIM * DIM];
__device__ bf16 g_Qh[SEQ * DIM], g_Ql[SEQ * DIM];     // 16MB each
__device__ bf16 g_Kh[SEQ * DIM], g_Kl[SEQ * DIM];
__device__ float g_W[SEQ * BAND];                     // 8MB
__device__ float g_Xsum[DIM];

// ---------------- PTX helpers (baseline ISA only, no sm_103a features) ----
__device__ __forceinline__ uint32_t smem_u32(const void* p) {
    uint32_t r;
    asm("{ .reg .u64 t; cvta.to.shared.u64 t, %1; cvt.u32.u64 %0, t; }"
        : "=r"(r) : "l"(p));
    return r;
}
__device__ __forceinline__ void ldm_x4(uint32_t* r, uint32_t addr) {
    asm volatile("ldmatrix.sync.aligned.m8n8.x4.shared.b16 {%0,%1,%2,%3}, [%4];"
                 : "=r"(r[0]), "=r"(r[1]), "=r"(r[2]), "=r"(r[3]) : "r"(addr));
}
__device__ __forceinline__ void mma16816(float* c, const uint32_t* a, const uint32_t* b) {
    asm volatile(
        "mma.sync.aligned.m16n8k16.row.col.f32.bf16.bf16.f32 "
        "{%0,%1,%2,%3}, {%4,%5,%6,%7}, {%8,%9}, {%0,%1,%2,%3};"
        : "+f"(c[0]), "+f"(c[1]), "+f"(c[2]), "+f"(c[3])
        : "r"(a[0]), "r"(a[1]), "r"(a[2]), "r"(a[3]), "r"(b[0]), "r"(b[1]));
}

#define KPAD 40   // bf16 elements per smem row (32 data + 8 pad) -> conflict-free ldmatrix

// ---------------------------------------------------------------------------
// Shared MMA mainloop: acc[128,128] += Ah*Bh^T + Ah*Bl^T + Al*Bh^T over K=1024.
// A rows arow0..+128 always valid; B rows bounds-checked when BCHECK.
// Layout: 8 warps as 2(m) x 4(n); warp tile 64x32; k-chunk 32, 32 chunks.
// ---------------------------------------------------------------------------
template <bool BCHECK>
__device__ __forceinline__ void mma_mainloop(
    const bf16* __restrict__ Ah, const bf16* __restrict__ Al, int arow0,
    const bf16* __restrict__ Bh, const bf16* __restrict__ Bl, int brow0,
    bf16* sAh, bf16* sAl, bf16* sBh, bf16* sBl,
    float acc[4][4][4])
{
    const int tid  = threadIdx.x;
    const int lane = tid & 31;
    const int wid  = tid >> 5;
    const int wm   = wid >> 2;   // 0..1
    const int wn   = wid & 3;    // 0..3

    // ldmatrix per-lane address offsets (bytes)
    const uint32_t aoff = (((lane & 15) * KPAD) + ((lane >> 4) << 3)) * 2;
    const uint32_t boff = ((((lane & 7) + ((lane >> 4) << 3)) * KPAD) +
                           (((lane >> 3) & 1) << 3)) * 2;
    const uint32_t aAh = smem_u32(sAh) + aoff + wm * 64 * KPAD * 2;
    const uint32_t aAl = smem_u32(sAl) + aoff + wm * 64 * KPAD * 2;
    const uint32_t bBh = smem_u32(sBh) + boff + wn * 32 * KPAD * 2;
    const uint32_t bBl = smem_u32(sBl) + boff + wn * 32 * KPAD * 2;

    const int lrow = tid >> 2;        // 0..63 (+64 on second pass)
    const int lcol = (tid & 3) * 8;   // bf16 column

    for (int kc = 0; kc < 32; kc++) {
        const int k0 = kc * 32;
        #pragma unroll
        for (int i = 0; i < 2; i++) {
            int row = lrow + i * 64;
            size_t ga = (size_t)(arow0 + row) * DIM + k0 + lcol;
            *(uint4*)(sAh + row * KPAD + lcol) = *(const uint4*)(Ah + ga);
            *(uint4*)(sAl + row * KPAD + lcol) = *(const uint4*)(Al + ga);
            uint4 vh = make_uint4(0, 0, 0, 0), vl = make_uint4(0, 0, 0, 0);
            int br = brow0 + row;
            if (!BCHECK || ((unsigned)br < (unsigned)SEQ)) {
                size_t gb = (size_t)br * DIM + k0 + lcol;
                vh = *(const uint4*)(Bh + gb);
                vl = *(const uint4*)(Bl + gb);
            }
            *(uint4*)(sBh + row * KPAD + lcol) = vh;
            *(uint4*)(sBl + row * KPAD + lcol) = vl;
        }
        __syncthreads();
        #pragma unroll
        for (int ks = 0; ks < 2; ks++) {
            const uint32_t ko = ks * 32;   // 16 bf16 = 32 bytes
            uint32_t bh[2][4], bl[2][4], a[4][4];
            #pragma unroll
            for (int nf2 = 0; nf2 < 2; nf2++) {
                ldm_x4(bh[nf2], bBh + nf2 * 16 * KPAD * 2 + ko);
                ldm_x4(bl[nf2], bBl + nf2 * 16 * KPAD * 2 + ko);
            }
            #pragma unroll
            for (int mf = 0; mf < 4; mf++)
                ldm_x4(a[mf], aAh + mf * 16 * KPAD * 2 + ko);
            #pragma unroll
            for (int mf = 0; mf < 4; mf++)
                #pragma unroll
                for (int nf = 0; nf < 4; nf++) {
                    mma16816(acc[mf][nf], a[mf], &bh[nf >> 1][(nf & 1) * 2]);
                    mma16816(acc[mf][nf], a[mf], &bl[nf >> 1][(nf & 1) * 2]);
                }
            #pragma unroll
            for (int mf = 0; mf < 4; mf++)
                ldm_x4(a[mf], aAl + mf * 16 * KPAD * 2 + ko);
            #pragma unroll
            for (int mf = 0; mf < 4; mf++)
                #pragma unroll
                for (int nf = 0; nf < 4; nf++)
                    mma16816(acc[mf][nf], a[mf], &bh[nf >> 1][(nf & 1) * 2]);
        }
        __syncthreads();
    }
}

// ---------------------------------------------------------------------------
// Kernel 0: split fp32 -> bf16 hi/lo for x, Wq, Wk (one fused launch)
// ---------------------------------------------------------------------------
#define N4X (SEQ * DIM / 4)
#define N4W (DIM * DIM / 4)
__global__ void split_all(const float* __restrict__ x,
                          const float* __restrict__ Wq,
                          const float* __restrict__ Wk)
{
    int i = blockIdx.x * 256 + threadIdx.x;
    const float* s;
    bf16 *dh, *dl;
    int off;
    if (i < N4X)            { s = x;  dh = g_xh;  dl = g_xl;  off = i; }
    else if (i < N4X + N4W) { s = Wq; dh = g_Wqh; dl = g_Wql; off = i - N4X; }
    else                    { s = Wk; dh = g_Wkh; dl = g_Wkl; off = i - N4X - N4W; }
    float4 v = ((const float4*)s)[off];
    bf16 h0 = __float2bfloat16(v.x), h1 = __float2bfloat16(v.y);
    bf16 h2 = __float2bfloat16(v.z), h3 = __float2bfloat16(v.w);
    __nv_bfloat162 hh0, hh1, ll0, ll1;
    hh0.x = h0; hh0.y = h1; hh1.x = h2; hh1.y = h3;
    ll0.x = __float2bfloat16(v.x - __bfloat162float(h0));
    ll0.y = __float2bfloat16(v.y - __bfloat162float(h1));
    ll1.x = __float2bfloat16(v.z - __bfloat162float(h2));
    ll1.y = __float2bfloat16(v.w - __bfloat162float(h3));
    ((__nv_bfloat162*)dh)[2 * off]     = hh0;
    ((__nv_bfloat162*)dh)[2 * off + 1] = hh1;
    ((__nv_bfloat162*)dl)[2 * off]     = ll0;
    ((__nv_bfloat162*)dl)[2 * off + 1] = ll1;
}

// ---------------------------------------------------------------------------
// Kernel 1: Q/K projection (tensor cores). z=0 -> Q, z=1 -> K.
// Epilogue adds bias, stores Q/K directly as bf16 hi/lo splits.
// ---------------------------------------------------------------------------
__global__ __launch_bounds__(256) void qk_mma(const float* __restrict__ bq,
                                              const float* __restrict__ bk)
{
    __shared__ bf16 sAh[128 * KPAD], sAl[128 * KPAD];
    __shared__ bf16 sBh[128 * KPAD], sBl[128 * KPAD];

    const int n0 = blockIdx.x * 128;
    const int m0 = blockIdx.y * 128;
    const bool isK = (blockIdx.z != 0);
    const bf16* Bh = isK ? g_Wkh : g_Wqh;
    const bf16* Bl = isK ? g_Wkl : g_Wql;
    const float* bias = isK ? bk : bq;
    bf16* Oh = isK ? g_Kh : g_Qh;
    bf16* Ol = isK ? g_Kl : g_Ql;

    float acc[4][4][4];
    #pragma unroll
    for (int a = 0; a < 4; a++)
        #pragma unroll
        for (int b = 0; b < 4; b++)
            #pragma unroll
            for (int c = 0; c < 4; c++) acc[a][b][c] = 0.f;

    mma_mainloop<false>(g_xh, g_xl, m0, Bh, Bl, n0, sAh, sAl, sBh, sBl, acc);

    const int lane = threadIdx.x & 31;
    const int wid  = threadIdx.x >> 5;
    const int wm = wid >> 2, wn = wid & 3;
    const int g = lane >> 2, t2 = (lane & 3) * 2;

    #pragma unroll
    for (int mf = 0; mf < 4; mf++) {
        int row = m0 + wm * 64 + mf * 16 + g;
        #pragma unroll
        for (int nf = 0; nf < 4; nf++) {
            int col = n0 + wn * 32 + nf * 8 + t2;
            float b0 = bias[col], b1 = bias[col + 1];
            #pragma unroll
            for (int h = 0; h < 2; h++) {   // h=0: rows g, h=1: rows g+8
                float v0 = acc[mf][nf][2 * h]     + b0;
                float v1 = acc[mf][nf][2 * h + 1] + b1;
                bf16 h0 = __float2bfloat16(v0), h1 = __float2bfloat16(v1);
                __nv_bfloat162 hh, ll;
                hh.x = h0; hh.y = h1;
                ll.x = __float2bfloat16(v0 - __bfloat162float(h0));
                ll.y = __float2bfloat16(v1 - __bfloat162float(h1));
                size_t o = (size_t)(row + 8 * h) * DIM + col;
                *(__nv_bfloat162*)(Oh + o) = hh;
                *(__nv_bfloat162*)(Ol + o) = ll;
            }
        }
    }
}

// ---------------------------------------------------------------------------
// Kernel 2: banded scores (tensor cores). 3 key subtiles per 128-query tile.
// Epilogue: expm1(score) into band buffer g_W.
// ---------------------------------------------------------------------------
__global__ __launch_bounds__(256) void score_mma()
{
    __shared__ bf16 sAh[128 * KPAD], sAl[128 * KPAD];
    __shared__ bf16 sBh[128 * KPAD], sBl[128 * KPAD];

    const int t0 = blockIdx.y * 128;
    const int kb = t0 - WIN + blockIdx.x * 128;

    float acc[4][4][4];
    #pragma unroll
    for (int a = 0; a < 4; a++)
        #pragma unroll
        for (int b = 0; b < 4; b++)
            #pragma unroll
            for (int c = 0; c < 4; c++) acc[a][b][c] = 0.f;

    mma_mainloop<true>(g_Qh, g_Ql, t0, g_Kh, g_Kl, kb, sAh, sAl, sBh, sBl, acc);

    const int lane = threadIdx.x & 31;
    const int wid  = threadIdx.x >> 5;
    const int wm = wid >> 2, wn = wid & 3;
    const int g = lane >> 2, t2 = (lane & 3) * 2;

    #pragma unroll
    for (int mf = 0; mf < 4; mf++) {
        #pragma unroll
        for (int nf = 0; nf < 4; nf++) {
            int s = kb + wn * 32 + nf * 8 + t2;
            if ((unsigned)s >= (unsigned)SEQ && (unsigned)(s + 1) >= (unsigned)SEQ)
                continue;
            #pragma unroll
            for (int h = 0; h < 2; h++) {
                int t = t0 + wm * 64 + mf * 16 + g + 8 * h;
                int j0 = s - t + WIN;
                if ((unsigned)s < (unsigned)SEQ && (unsigned)j0 < (unsigned)BAND)
                    g_W[(size_t)t * BAND + j0] = expm1f(acc[mf][nf][2 * h]);
                int j1 = j0 + 1;
                if ((unsigned)(s + 1) < (unsigned)SEQ && (unsigned)j1 < (unsigned)BAND)
                    g_W[(size_t)t * BAND + j1] = expm1f(acc[mf][nf][2 * h + 1]);
            }
        }
    }
}

// ---------------------------------------------------------------------------
// Kernel 3: column sums of x
// ---------------------------------------------------------------------------
__global__ void xsum_zero() { g_Xsum[blockIdx.x * 256 + threadIdx.x] = 0.f; }

__global__ void xsum_acc(const float* __restrict__ x)
{
    int d  = blockIdx.x * 256 + threadIdx.x;
    int s0 = blockIdx.y * 128;
    float sum = 0.f;
    #pragma unroll 4
    for (int i = 0; i < 128; i++)
        sum += x[(size_t)(s0 + i) * DIM + d];
    atomicAdd(&g_Xsum[d], sum);
}

// ---------------------------------------------------------------------------
// Kernel 4: out[t][d] = (sum_s w[t][s] x[s][d] + Xsum[d]) / (sum_s w + SEQ)
// SGEMM-style 128x128 tile, BK=16, 256 threads, 8x8 accum + per-query denom.
// ---------------------------------------------------------------------------
__global__ __launch_bounds__(256) void out_kernel(const float* __restrict__ x,
                                                  float* __restrict__ out)
{
    const int t0 = blockIdx.y * 128;
    const int d0 = blockIdx.x * 128;
    const int tid = threadIdx.x;
    const int tx = tid & 15;
    const int ty = tid >> 4;

    __shared__ float Ws[16][132];
    __shared__ float Xs[16][132];

    float acc[8][8];
    float den[8];
    #pragma unroll
    for (int i = 0; i < 8; i++) {
        den[i] = 0.f;
        #pragma unroll
        for (int j = 0; j < 8; j++) acc[i][j] = 0.f;
    }

    for (int c = 0; c < 24; c++) {
        const int sbk = t0 - WIN + c * 16;
        #pragma unroll
        for (int i = 0; i < 2; i++) {
            int v = tid + i * 256;
            int row = v >> 5, c4 = v & 31;
            int s = sbk + row;
            float4 xv = make_float4(0.f, 0.f, 0.f, 0.f);
            if ((unsigned)s < (unsigned)SEQ)
                xv = *(const float4*)(x + (size_t)s * DIM + d0 + c4 * 4);
            *(float4*)&Xs[row][c4 * 4] = xv;
        }
        #pragma unroll
        for (int i = 0; i < 8; i++) {
            int v = tid + i * 256;
            int q = v >> 4, k = v & 15;
            int t = t0 + q;
            int s = sbk + k;
            int j = s - t + WIN;
            float w = 0.f;
            if ((unsigned)s < (unsigned)SEQ && (unsigned)j < (unsigned)BAND)
                w = g_W[(size_t)t * BAND + j];
            Ws[k][q] = w;
        }
        __syncthreads();
        #pragma unroll
        for (int k = 0; k < 16; k++) {
            float ar[8], br[8];
            *(float4*)&ar[0] = *(const float4*)&Ws[k][ty * 8];
            *(float4*)&ar[4] = *(const float4*)&Ws[k][ty * 8 + 4];
            *(float4*)&br[0] = *(const float4*)&Xs[k][tx * 8];
            *(float4*)&br[4] = *(const float4*)&Xs[k][tx * 8 + 4];
            #pragma unroll
            for (int i = 0; i < 8; i++) {
                den[i] += ar[i];
                #pragma unroll
                for (int j = 0; j < 8; j++)
                    acc[i][j] += ar[i] * br[j];
            }
        }
        __syncthreads();
    }

    float xs[8];
    *(float4*)&xs[0] = *(const float4*)(g_Xsum + d0 + tx * 8);
    *(float4*)&xs[4] = *(const float4*)(g_Xsum + d0 + tx * 8 + 4);
    #pragma unroll
    for (int i = 0; i < 8; i++) {
        float dinv = 1.0f / (den[i] + (float)SEQ);
        float* op = out + (size_t)(t0 + ty * 8 + i) * DIM + d0 + tx * 8;
        float4 o0 = make_float4((acc[i][0] + xs[0]) * dinv, (acc[i][1] + xs[1]) * dinv,
                                (acc[i][2] + xs[2]) * dinv, (acc[i][3] + xs[3]) * dinv);
        float4 o1 = make_float4((acc[i][4] + xs[4]) * dinv, (acc[i][5] + xs[5]) * dinv,
                                (acc[i][6] + xs[6]) * dinv, (acc[i][7] + xs[7]) * dinv);
        *(float4*)op       = o0;
        *(float4*)(op + 4) = o1;
    }
}

// ---------------------------------------------------------------------------
extern "C" void kernel_launch(void* const* d_in, const int* in_sizes, int n_in,
                              void* d_out, int out_size)
{
    const float* x  = (const float*)d_in[0];
    const float* Wq = (const float*)d_in[1];
    const float* bq = (const float*)d_in[2];
    const float* Wk = (const float*)d_in[3];
    const float* bk = (const float*)d_in[4];
    float* out = (float*)d_out;

    // 0) fp32 -> bf16 hi/lo splits of x, Wq, Wk
    split_all<<<(N4X + 2 * N4W) / 256, 256>>>(x, Wq, Wk);

    // 1) Q/K projections on tensor cores (3-term split-bf16 emulated fp32)
    qk_mma<<<dim3(DIM / 128, SEQ / 128, 2), 256>>>(bq, bk);

    // 2) column sums of x
    xsum_zero<<<DIM / 256, 256>>>();
    xsum_acc<<<dim3(DIM / 256, SEQ / 128), 256>>>(x);

    // 3) banded scores -> expm1 weights, on tensor cores
    score_mma<<<dim3(3, SEQ / 128), 256>>>();

    // 4) banded weighted sum + normalization (fp32 FFMA)
    out_kernel<<<dim3(DIM / 128, SEQ / 128), 256>>>(x, out);
}